// round 1
// baseline (speedup 1.0000x reference)
#include <cuda_runtime.h>
#include <cstdint>

#define B_    8
#define T_    4096
#define R_    1024
#define F_    64
#define I_    32
#define KTOT  96            // F_ + I_
#define NBLK  128           // scan blocks (8 rows of W_hh each)
#define NTHR  256

// ---------------- device scratch (no allocations allowed) ----------------
__device__ float    g_h[2][R_][B_];   // ping-pong hidden state, [buf][k][b]
__device__ unsigned g_bar;            // grid barrier counter

// ---------------- helpers ----------------
__device__ __forceinline__ unsigned long long pack2(float a, float b) {
    unsigned long long r;
    asm("mov.b64 %0, {%1, %2};" : "=l"(r) : "f"(a), "f"(b));
    return r;
}
__device__ __forceinline__ void fma2(unsigned long long& d, unsigned long long a, unsigned long long b) {
    asm("fma.rn.f32x2 %0, %1, %2, %0;" : "+l"(d) : "l"(a), "l"(b));
}
__device__ __forceinline__ unsigned long long add2(unsigned long long a, unsigned long long b) {
    unsigned long long r;
    asm("add.rn.f32x2 %0, %1, %2;" : "=l"(r) : "l"(a), "l"(b));
    return r;
}
__device__ __forceinline__ float2 unpack2(unsigned long long v) {
    float2 f;
    asm("mov.b64 {%0, %1}, %2;" : "=f"(f.x), "=f"(f.y) : "l"(v));
    return f;
}

template <int HALF>
__device__ __forceinline__ void reduce_round(unsigned long long* a, int lane, int d) {
    const bool hi = (lane & d) != 0;
#pragma unroll
    for (int i = 0; i < HALF; i++) {
        unsigned long long send = hi ? a[i] : a[i + HALF];
        unsigned long long keep = hi ? a[i + HALF] : a[i];
        unsigned long long recv = __shfl_xor_sync(0xffffffffu, send, d);
        a[i] = add2(keep, recv);
    }
}

// ---------------- reset: zero h buffer + barrier counter ----------------
__global__ void reset_kernel() {
    int idx = blockIdx.x * blockDim.x + threadIdx.x;
    float* p = &g_h[0][0][0];
    const int n = 2 * R_ * B_;
    for (int i = idx; i < n; i += gridDim.x * blockDim.x) p[i] = 0.0f;
    if (idx == 0) g_bar = 0u;
}

// ---------------- drive GEMM: out[bt][r] = X @ [Wfb|Win]^T + bias ----------------
// tile: 64 bt-rows x 128 r-cols, 256 threads, thread tile 4x8
#define DRIVE_SMEM ((64 + 128) * 97 * 4)

__global__ __launch_bounds__(256) void drive_kernel(
    const float* __restrict__ fb, const float* __restrict__ drv,
    const float* __restrict__ Wfb, const float* __restrict__ Win,
    const float* __restrict__ bias, float* __restrict__ out)
{
    extern __shared__ float smem[];
    float (*xs)[97]  = (float (*)[97])smem;              // [64][97]
    float (*wsh)[97] = (float (*)[97])(smem + 64 * 97);  // [128][97]

    const int r0  = blockIdx.x * 128;
    const int bt0 = blockIdx.y * 64;
    const int tid = threadIdx.x;

    for (int idx = tid; idx < 64 * KTOT; idx += 256) {
        int row = idx / KTOT, col = idx - row * KTOT;
        float v = (col < F_) ? fb[(size_t)(bt0 + row) * F_ + col]
                             : drv[(size_t)(bt0 + row) * I_ + (col - F_)];
        xs[row][col] = v;
    }
    for (int idx = tid; idx < 128 * KTOT; idx += 256) {
        int row = idx / KTOT, col = idx - row * KTOT;
        int r = r0 + row;
        float v = (col < F_) ? Wfb[r * F_ + col] : Win[r * I_ + (col - F_)];
        wsh[row][col] = v;
    }
    __syncthreads();

    const int tx = tid & 15;   // r = r0 + tx + 16*j  (stride-1 across lanes -> no bank conflicts)
    const int ty = tid >> 4;   // bt = bt0 + ty*4 + i

    float acc[4][8];
#pragma unroll
    for (int i = 0; i < 4; i++)
#pragma unroll
        for (int j = 0; j < 8; j++) acc[i][j] = 0.0f;

    for (int f = 0; f < KTOT; f++) {
        float x0 = xs[ty * 4 + 0][f];
        float x1 = xs[ty * 4 + 1][f];
        float x2 = xs[ty * 4 + 2][f];
        float x3 = xs[ty * 4 + 3][f];
        float w[8];
#pragma unroll
        for (int j = 0; j < 8; j++) w[j] = wsh[tx + 16 * j][f];
#pragma unroll
        for (int j = 0; j < 8; j++) {
            acc[0][j] = fmaf(x0, w[j], acc[0][j]);
            acc[1][j] = fmaf(x1, w[j], acc[1][j]);
            acc[2][j] = fmaf(x2, w[j], acc[2][j]);
            acc[3][j] = fmaf(x3, w[j], acc[3][j]);
        }
    }

#pragma unroll
    for (int j = 0; j < 8; j++) {
        int r = r0 + tx + 16 * j;
        float bv = bias[r];
#pragma unroll
        for (int i = 0; i < 4; i++) {
            size_t bt = (size_t)bt0 + ty * 4 + i;
            out[bt * R_ + r] = acc[i][j] + bv;
        }
    }
}

// ---------------- sequential scan: persistent, grid-barrier per step ----------------
// block b owns rows r0..r0+7 of W_hh. thread tid: half = tid&1 (b 0..3 vs 4..7),
// kq = tid>>1, covers k = kq + 128*i (i<8). W slice pre-duplicated in regs as f32x2.
__global__ __launch_bounds__(NTHR, 1) void scan_kernel(
    const float* __restrict__ Whh, float* __restrict__ out)
{
    __shared__ float2 partials[8][32];

    const int tid  = threadIdx.x;
    const int lane = tid & 31;
    const int warp = tid >> 5;
    const int r0   = blockIdx.x * 8;
    const int half = tid & 1;
    const int kq   = tid >> 1;

    // preload W_hh slice, duplicated pairs {w,w}
    unsigned long long wd[8][8];
#pragma unroll
    for (int i = 0; i < 8; i++) {
        int k = kq + i * 128;
#pragma unroll
        for (int j = 0; j < 8; j++) {
            float w = Whh[(size_t)(r0 + j) * R_ + k];
            wd[i][j] = pack2(w, w);
        }
    }

    const float alpha = 0.9f;
    const float onem  = 1.0f - alpha;

    for (int t = 0; t < T_; t++) {
        const int cur = t & 1, nxt = cur ^ 1;

        unsigned long long acc[16];
#pragma unroll
        for (int o = 0; o < 16; o++) acc[o] = 0ull;

        const float4* hsrc = reinterpret_cast<const float4*>(&g_h[cur][0][0]);
#pragma unroll
        for (int i = 0; i < 8; i++) {
            int k = kq + i * 128;
            float4 h4 = __ldcg(hsrc + (k * 2 + half));  // h[k][4*half .. 4*half+3]
            unsigned long long h01 = pack2(h4.x, h4.y);
            unsigned long long h23 = pack2(h4.z, h4.w);
#pragma unroll
            for (int j = 0; j < 8; j++) {
                fma2(acc[j * 2 + 0], h01, wd[i][j]);
                fma2(acc[j * 2 + 1], h23, wd[i][j]);
            }
        }

        // log-halving warp reduction among the 16 lanes sharing `half`
        reduce_round<8>(acc, lane, 2);
        reduce_round<4>(acc, lane, 4);
        reduce_round<2>(acc, lane, 8);
        reduce_round<1>(acc, lane, 16);

        // lane ends owning output o = 8*b1 + 4*b2 + 2*b3 + b4  (bits of lane)
        {
            int o = (((lane >> 1) & 1) << 3) | (((lane >> 2) & 1) << 2) |
                    (((lane >> 3) & 1) << 1) | ((lane >> 4) & 1);
            int j = o >> 1, q = o & 1;
            int p = 2 * half + q;           // batch-pair index 0..3
            partials[warp][j * 4 + p] = unpack2(acc[0]);
        }
        __syncthreads();

        if (warp == 0) {
            float2 s = partials[0][lane];
#pragma unroll
            for (int w = 1; w < 8; w++) {
                float2 pw = partials[w][lane];
                s.x += pw.x; s.y += pw.y;
            }
            int j = lane >> 2, p = lane & 3;
            int r = r0 + j;
            int b0 = 2 * p, b1 = b0 + 1;
            size_t i0 = ((size_t)b0 * T_ + t) * R_ + r;
            size_t i1 = ((size_t)b1 * T_ + t) * R_ + r;
            float u0 = out[i0];                 // drive value (in-place)
            float u1 = out[i1];
            float hp0 = __ldcg(&g_h[cur][r][b0]);
            float hp1 = __ldcg(&g_h[cur][r][b1]);
            float v0 = tanhf(onem * hp0 + alpha * (u0 + s.x));
            float v1 = tanhf(onem * hp1 + alpha * (u1 + s.y));
            out[i0] = v0;
            out[i1] = v1;
            __stcg(&g_h[nxt][r][b0], v0);
            __stcg(&g_h[nxt][r][b1], v1);
            __threadfence();
        }
        __syncthreads();

        if (t < T_ - 1) {
            if (tid == 0) {
                atomicAdd(&g_bar, 1u);
                const unsigned target = (unsigned)gridDim.x * (unsigned)(t + 1);
                unsigned v;
                do {
                    asm volatile("ld.acquire.gpu.u32 %0, [%1];"
                                 : "=r"(v) : "l"(&g_bar) : "memory");
                } while (v < target);
            }
            __syncthreads();
        }
    }
}

// ---------------- launch ----------------
extern "C" void kernel_launch(void* const* d_in, const int* in_sizes, int n_in,
                              void* d_out, int out_size)
{
    (void)in_sizes; (void)n_in; (void)out_size;
    const float* fb   = (const float*)d_in[0];
    const float* drv  = (const float*)d_in[1];
    const float* Wfb  = (const float*)d_in[2];
    const float* Win  = (const float*)d_in[3];
    const float* Whh  = (const float*)d_in[4];
    const float* bias = (const float*)d_in[5];
    float* out = (float*)d_out;

    cudaFuncSetAttribute(drive_kernel, cudaFuncAttributeMaxDynamicSharedMemorySize, DRIVE_SMEM);

    reset_kernel<<<16, 256>>>();

    dim3 dgrid(R_ / 128, (B_ * T_) / 64);
    drive_kernel<<<dgrid, 256, DRIVE_SMEM>>>(fb, drv, Wfb, Win, bias, out);

    scan_kernel<<<NBLK, NTHR>>>(Whh, out);
}